// round 1
// baseline (speedup 1.0000x reference)
#include <cuda_runtime.h>
#include <cuda_bf16.h>

// NeighborListForTraining: 2000 molecules x 64 atoms, all ordered intra-mol
// pairs (P = 2000*4032 = 8,064,000). Output layout (float32, concatenated):
//   [0   ,  P) : i_idx
//   [P   , 2P) : j_idx
//   [2P  , 3P) : d_ij  (0 if d > 5)
//   [3P  , 6P) : r_ij  (row-major 3/pair, 0 if d > 5)
//
// Store-bound kernel: 193.5 MB of writes, ~1.5 MB of cached reads.
// One thread handles 4 consecutive pairs -> 6x STG.128, fully coalesced.

#define NPM   64                 // atoms per molecule
#define PPM   (NPM * (NPM - 1))  // 4032 pairs per molecule (divisible by 4)
#define CUT   5.0f

__global__ __launch_bounds__(256)
void neighborlist_kernel(const float* __restrict__ pos,
                         float* __restrict__ out,
                         int n_groups, int n_pairs_total)
{
    int g = blockIdx.x * blockDim.x + threadIdx.x;
    if (g >= n_groups) return;

    const int p0 = g * 4;                 // first pair of this group
    const int m  = p0 / PPM;              // molecule (magic-multiply div)
    const int q0 = p0 - m * PPM;          // local pair index within molecule
    const float* __restrict__ mp = pos + (size_t)m * NPM * 3;
    const int atom_base = m * NPM;

    float iv[4], jv[4], dv[4], rx[4], ry[4], rz[4];

    #pragma unroll
    for (int k = 0; k < 4; ++k) {
        int q  = q0 + k;
        int i  = q / 63;                  // magic-multiply div by 63
        int jj = q - i * 63;
        int j  = jj + (jj >= i ? 1 : 0);  // skip diagonal

        float xi = __ldg(mp + 3 * i + 0);
        float yi = __ldg(mp + 3 * i + 1);
        float zi = __ldg(mp + 3 * i + 2);
        float xj = __ldg(mp + 3 * j + 0);
        float yj = __ldg(mp + 3 * j + 1);
        float zj = __ldg(mp + 3 * j + 2);

        float dx = xj - xi, dy = yj - yi, dz = zj - zi;
        float r2 = fmaf(dx, dx, fmaf(dy, dy, dz * dz));
        float d;
        asm("sqrt.approx.f32 %0, %1;" : "=f"(d) : "f"(r2));

        bool in = (d <= CUT);
        dv[k] = in ? d  : 0.0f;
        rx[k] = in ? dx : 0.0f;
        ry[k] = in ? dy : 0.0f;
        rz[k] = in ? dz : 0.0f;
        iv[k] = (float)(atom_base + i);
        jv[k] = (float)(atom_base + j);
    }

    const size_t P = (size_t)n_pairs_total;

    // i_idx region
    reinterpret_cast<float4*>(out)[g]          = make_float4(iv[0], iv[1], iv[2], iv[3]);
    // j_idx region
    reinterpret_cast<float4*>(out + P)[g]      = make_float4(jv[0], jv[1], jv[2], jv[3]);
    // d_ij region
    reinterpret_cast<float4*>(out + 2 * P)[g]  = make_float4(dv[0], dv[1], dv[2], dv[3]);
    // r_ij region: 12 contiguous floats per group -> 3x float4
    float4* rbase = reinterpret_cast<float4*>(out + 3 * P) + (size_t)g * 3;
    rbase[0] = make_float4(rx[0], ry[0], rz[0], rx[1]);
    rbase[1] = make_float4(ry[1], rz[1], rx[2], ry[2]);
    rbase[2] = make_float4(rz[2], rx[3], ry[3], rz[3]);
}

extern "C" void kernel_launch(void* const* d_in, const int* in_sizes, int n_in,
                              void* d_out, int out_size)
{
    const float* pos = (const float*)d_in[0];

    int n_atoms       = in_sizes[0] / 3;     // 128000
    int n_mols        = n_atoms / NPM;       // 2000
    int n_pairs_total = n_mols * PPM;        // 8,064,000
    int n_groups      = n_pairs_total / 4;   // 2,016,000

    float* out = (float*)d_out;

    int threads = 256;
    int blocks  = (n_groups + threads - 1) / threads;   // 7875
    neighborlist_kernel<<<blocks, threads>>>(pos, out, n_groups, n_pairs_total);
}